// round 12
// baseline (speedup 1.0000x reference)
#include <cuda_runtime.h>
#include <cuda_bf16.h>
#include <cstdint>

#define B_  4
#define C_  256
#define N_  4096
#define ESC  4.0f         // E -> s8 scale (exp(S) <= ~22 -> <= 88)
#define VSC2 262144.0f    // vs -> s8 scale (2^18)

// ---------------------------------------------------------------------------
// Scratch (__device__ globals; allocation-free rule)
// ---------------------------------------------------------------------------
__device__ __align__(16) __nv_bfloat16  g_xh[(size_t)B_ * N_ * C_];   // [b][n][c] bf16 (8MB)
__device__ __align__(16) __nv_bfloat16  g_qkh[B_ * N_ * 64];          // [b][n][q|k] bf16 (2MB)
__device__ __align__(16) uint8_t        g_vs8[(size_t)B_ * C_ * N_];  // [b][c][m] s8 (4MB)
__device__ __align__(16) uint8_t        g_E8[(size_t)B_ * N_ * N_];   // [b][n][m] s8 (64MB)
__device__ float                        g_R[B_ * N_];                 // 1/L[m]

// ---------------------------------------------------------------------------
// PTX helpers (base sm_80+ ISA only — harness targets plain sm_103)
// ---------------------------------------------------------------------------
__device__ __forceinline__ uint32_t smem_u32(const void* p) {
    uint32_t a;
    asm("{ .reg .u64 t; cvta.to.shared.u64 t, %1; cvt.u32.u64 %0, t; }" : "=r"(a) : "l"(p));
    return a;
}
#define CP_ASYNC16(dst, src) \
    asm volatile("cp.async.cg.shared.global [%0], [%1], 16;" :: "r"(dst), "l"(src))
#define CP_COMMIT()  asm volatile("cp.async.commit_group;" ::: "memory")
#define CP_WAIT0()   asm volatile("cp.async.wait_group 0;" ::: "memory")

#define LDMATRIX_X4(r0, r1, r2, r3, addr) \
    asm volatile("ldmatrix.sync.aligned.m8n8.x4.shared.b16 {%0,%1,%2,%3}, [%4];" \
                 : "=r"(r0), "=r"(r1), "=r"(r2), "=r"(r3) : "r"(addr))

#define MMA_BF16(d, a, b0v, b1v) \
    asm volatile("mma.sync.aligned.m16n8k16.row.col.f32.bf16.bf16.f32 " \
                 "{%0,%1,%2,%3}, {%4,%5,%6,%7}, {%8,%9}, {%0,%1,%2,%3};" \
                 : "+f"((d)[0]), "+f"((d)[1]), "+f"((d)[2]), "+f"((d)[3]) \
                 : "r"((a)[0]), "r"((a)[1]), "r"((a)[2]), "r"((a)[3]), \
                   "r"(b0v), "r"(b1v))

#define MMA_S8(d, a, b0v, b1v) \
    asm volatile("mma.sync.aligned.m16n8k32.row.col.s32.s8.s8.s32 " \
                 "{%0,%1,%2,%3}, {%4,%5,%6,%7}, {%8,%9}, {%0,%1,%2,%3};" \
                 : "+r"((d)[0]), "+r"((d)[1]), "+r"((d)[2]), "+r"((d)[3]) \
                 : "r"((a)[0]), "r"((a)[1]), "r"((a)[2]), "r"((a)[3]), \
                   "r"(b0v), "r"(b1v))

// float -> s8 (round-nearest, saturate), returned in low byte
__device__ __forceinline__ uint32_t f_s8(float v) {
    uint16_t r;
    asm("cvt.rni.sat.s8.f32 %0, %1;" : "=h"(r) : "f"(v));
    return (uint32_t)r & 0xFFu;
}
__device__ __forceinline__ uint16_t f2_s8x2(float lo, float hi) {
    return (uint16_t)(f_s8(lo) | (f_s8(hi) << 8));
}

// ---------------------------------------------------------------------------
// K0: transpose + convert x [b][c][n] fp32 -> g_xh [b][n][c] bf16
// ---------------------------------------------------------------------------
__global__ void xpose_kernel(const float* __restrict__ x) {
    __shared__ float xsm[64][68];
    const int n0 = blockIdx.x * 64;
    const int c0 = blockIdx.y * 64;
    const int b  = blockIdx.z;
    const int tid = threadIdx.x;

#pragma unroll
    for (int t = 0; t < 4; t++) {
        int idx = tid + t * 256;
        int cc = idx >> 4, q = idx & 15;
        *(float4*)&xsm[cc][q * 4] = *(const float4*)&x[((size_t)(b * C_ + c0 + cc)) * N_ + n0 + q * 4];
    }
    __syncthreads();
#pragma unroll
    for (int t = 0; t < 8; t++) {
        int idx = tid + t * 256;
        int nl = idx >> 5, pr = idx & 31;
        __nv_bfloat162 p;
        p.x = __float2bfloat16(xsm[pr * 2][nl]);
        p.y = __float2bfloat16(xsm[pr * 2 + 1][nl]);
        *(__nv_bfloat162*)&g_xh[((size_t)(b * N_ + n0 + nl)) * C_ + c0 + pr * 2] = p;
    }
}

// ---------------------------------------------------------------------------
// K1: q/k projection via HMMA (unchanged)
// ---------------------------------------------------------------------------
#define K1_WOFF  36864
#define K1_BOFF  (K1_WOFF + 64 * 528)
#define K1_SMEM  (K1_BOFF + 256)

__global__ __launch_bounds__(256, 1) void proj_qk_mma(
        const float* __restrict__ Wq, const float* __restrict__ bq,
        const float* __restrict__ Wk, const float* __restrict__ bk) {
    extern __shared__ char smem[];
    const uint32_t sbase = smem_u32(smem);
    const uint32_t wsm   = sbase + K1_WOFF;
    float* bsm = (float*)(smem + K1_BOFF);

    const int tid  = threadIdx.x;
    const int wid  = tid >> 5;
    const int lane = tid & 31;
    const int b    = blockIdx.y;
    const int n0   = blockIdx.x * 128;
    const int lrow  = lane & 15;
    const int lcolB = (lane >> 4) * 16;

    const __nv_bfloat16* Xb = g_xh + (size_t)(b * N_ + n0) * C_;

#pragma unroll
    for (int t = 0; t < 4; t++) {
        int idx = tid + t * 256;
        int row = idx >> 3, c16 = idx & 7;
        CP_ASYNC16(sbase + row * 144 + c16 * 16, Xb + (size_t)row * C_ + c16 * 8);
    }
    CP_COMMIT();

#pragma unroll
    for (int t = 0; t < 64; t++) {
        int idx = tid + t * 256;
        int co = idx >> 8, c = idx & 255;
        float v = (co < 32) ? Wq[co * 256 + c] : Wk[(co - 32) * 256 + c];
        *(__nv_bfloat16*)(smem + K1_WOFF + co * 528 + c * 2) = __float2bfloat16(v);
    }
    if (tid < 64) bsm[tid] = (tid < 32) ? bq[tid] : bk[tid - 32];

    float acc[8][4];
#pragma unroll
    for (int nt = 0; nt < 8; nt++)
#pragma unroll
        for (int r = 0; r < 4; r++) acc[nt][r] = 0.0f;

    for (int kc = 0; kc < 4; kc++) {
        const int s = kc & 1;
        CP_WAIT0();
        __syncthreads();

        if (kc + 1 < 4) {
            const uint32_t sd = sbase + (s ^ 1) * 18432;
            const int k0n = (kc + 1) * 64;
#pragma unroll
            for (int t = 0; t < 4; t++) {
                int idx = tid + t * 256;
                int row = idx >> 3, c16 = idx & 7;
                CP_ASYNC16(sd + row * 144 + c16 * 16, Xb + (size_t)row * C_ + k0n + c16 * 8);
            }
            CP_COMMIT();
        }

        const uint32_t sa = sbase + s * 18432;
#pragma unroll
        for (int kk = 0; kk < 4; kk++) {
            uint32_t a[4];
            LDMATRIX_X4(a[0], a[1], a[2], a[3],
                        sa + (wid * 16 + lrow) * 144 + kk * 32 + lcolB);
            uint32_t br[4][4];
#pragma unroll
            for (int bt = 0; bt < 4; bt++)
                LDMATRIX_X4(br[bt][0], br[bt][1], br[bt][2], br[bt][3],
                            wsm + (bt * 16 + lrow) * 528 + (kc * 64 + kk * 16) * 2 + lcolB);
#pragma unroll
            for (int nt = 0; nt < 8; nt++) {
                const int bt = nt >> 1, sel = nt & 1;
                MMA_BF16(acc[nt], a, br[bt][sel], br[bt][sel + 2]);
            }
        }
    }

    const int nrow = n0 + wid * 16 + (lane >> 2);
#pragma unroll
    for (int nt = 0; nt < 8; nt++) {
        const int co = nt * 8 + (lane & 3) * 2;
        const float b0 = bsm[co], b1 = bsm[co + 1];
        __nv_bfloat162 p0, p1;
        p0.x = __float2bfloat16(acc[nt][0] + b0);
        p0.y = __float2bfloat16(acc[nt][1] + b1);
        p1.x = __float2bfloat16(acc[nt][2] + b0);
        p1.y = __float2bfloat16(acc[nt][3] + b1);
        *(__nv_bfloat162*)&g_qkh[((size_t)(b * N_ + nrow)) * 64 + co]       = p0;
        *(__nv_bfloat162*)&g_qkh[((size_t)(b * N_ + nrow + 8)) * 64 + co]   = p1;
    }
}

// ---------------------------------------------------------------------------
// K2: stats — S via HMMA, exp (MUFU); writes E (s8, scaled by ESC) AND
//     column sums -> g_R = 1/L. grid (N/64 m-slabs, B) = 256 CTAs, 256 thr.
//     esm row stride = 80 B (16-aligned; 72 caused the R11 misalignment).
// ---------------------------------------------------------------------------
#define E_ROWB 80

__global__ __launch_bounds__(256, 2) void stats_i8() {
    __shared__ __align__(16) char ksm_s[64 * 80];
    __shared__ __align__(16) char qsm_s[2 * 128 * 80];
    __shared__ __align__(16) char esm_s[128 * E_ROWB];
    __shared__ float redsm[8 * 64];
    const uint32_t ksm = smem_u32(ksm_s);
    const uint32_t qsm = smem_u32(qsm_s);

    const int tid  = threadIdx.x;
    const int wid  = tid >> 5;
    const int lane = tid & 31;
    const int b    = blockIdx.y;
    const int m0   = blockIdx.x * 64;
    const int lrow  = lane & 15;
    const int lcolB = (lane >> 4) * 16;

    const __nv_bfloat16* QK = g_qkh + (size_t)b * N_ * 64;

    // k-slab: 64 m-rows x 32 d (at +32)
    {
        int row = tid >> 2, c16 = tid & 3;
        CP_ASYNC16(ksm + row * 80 + c16 * 16, QK + (size_t)(m0 + row) * 64 + 32 + c16 * 8);
    }
    // q tile 0: 128 n-rows x 32 d
#pragma unroll
    for (int t = 0; t < 2; t++) {
        int idx = tid + t * 256;
        int row = idx >> 2, c16 = idx & 3;
        CP_ASYNC16(qsm + row * 80 + c16 * 16, QK + (size_t)row * 64 + c16 * 8);
    }
    CP_COMMIT();

    float csum[8][2];
#pragma unroll
    for (int u = 0; u < 8; u++) { csum[u][0] = 0.0f; csum[u][1] = 0.0f; }

    for (int nt = 0; nt < 32; nt++) {
        const int s = nt & 1;
        CP_WAIT0();
        __syncthreads();          // q(nt) ready; esm copy of nt-1 done

        if (nt + 1 < 32) {
            const int n0n = (nt + 1) * 128;
            const uint32_t qd = qsm + (s ^ 1) * 10240;
#pragma unroll
            for (int t = 0; t < 2; t++) {
                int idx = tid + t * 256;
                int row = idx >> 2, c16 = idx & 3;
                CP_ASYNC16(qd + row * 80 + c16 * 16, QK + (size_t)(n0n + row) * 64 + c16 * 8);
            }
            CP_COMMIT();
        }

        const uint32_t qs = qsm + s * 10240;

        float acc[8][4];
#pragma unroll
        for (int u = 0; u < 8; u++)
#pragma unroll
            for (int r = 0; r < 4; r++) acc[u][r] = 0.0f;

#pragma unroll
        for (int kk = 0; kk < 2; kk++) {
            const int kb = kk * 32 + lcolB;
            uint32_t a[4];
            LDMATRIX_X4(a[0], a[1], a[2], a[3], qs + (wid * 16 + lrow) * 80 + kb);
            uint32_t br[4][4];
#pragma unroll
            for (int bt = 0; bt < 4; bt++)
                LDMATRIX_X4(br[bt][0], br[bt][1], br[bt][2], br[bt][3],
                            ksm + (bt * 16 + lrow) * 80 + kb);
#pragma unroll
            for (int u = 0; u < 8; u++) {
                const int bt = u >> 1, sel = u & 1;
                MMA_BF16(acc[u], a, br[bt][sel], br[bt][sel + 2]);
            }
        }

        // exp -> csum (fp32) + quantize -> esm (s8)
        const int row = wid * 16 + (lane >> 2);
#pragma unroll
        for (int u = 0; u < 8; u++) {
            const int col = u * 8 + (lane & 3) * 2;
            float e0 = __expf(acc[u][0]);
            float e1 = __expf(acc[u][1]);
            float e2 = __expf(acc[u][2]);
            float e3 = __expf(acc[u][3]);
            csum[u][0] += e0 + e2;
            csum[u][1] += e1 + e3;
            *(uint16_t*)(esm_s + row * E_ROWB + col)       = f2_s8x2(e0 * ESC, e1 * ESC);
            *(uint16_t*)(esm_s + (row + 8) * E_ROWB + col) = f2_s8x2(e2 * ESC, e3 * ESC);
        }
        __syncthreads();

        // coalesced E store: 128 rows x 64B
        const int n0g = nt * 128;
#pragma unroll
        for (int t = 0; t < 2; t++) {
            int idx = tid + t * 256;
            int row2 = idx >> 2, q16 = idx & 3;
            float4 v = *(float4*)(esm_s + row2 * E_ROWB + q16 * 16);
            *(float4*)&g_E8[((size_t)(b * N_ + n0g + row2)) * N_ + m0 + q16 * 16] = v;
        }
    }

    // reduce column sums over rows (lanes sharing lane&3 hold same columns)
#pragma unroll
    for (int off = 16; off >= 4; off >>= 1)
#pragma unroll
        for (int u = 0; u < 8; u++) {
            csum[u][0] += __shfl_down_sync(0xffffffffu, csum[u][0], off);
            csum[u][1] += __shfl_down_sync(0xffffffffu, csum[u][1], off);
        }
    if (lane < 4) {
#pragma unroll
        for (int u = 0; u < 8; u++) {
            redsm[wid * 64 + u * 8 + lane * 2 + 0] = csum[u][0];
            redsm[wid * 64 + u * 8 + lane * 2 + 1] = csum[u][1];
        }
    }
    __syncthreads();
    if (tid < 64) {
        float L = 0.0f;
#pragma unroll
        for (int w = 0; w < 8; w++) L += redsm[w * 64 + tid];
        g_R[b * N_ + m0 + tid] = 1.0f / L;
    }
}

// ---------------------------------------------------------------------------
// K3: v projection via HMMA + bias, * (VSC2/L), stored TRANSPOSED s8.
// ---------------------------------------------------------------------------
#define K3_WOFF  36864
#define K3_BOFF  (K3_WOFF + 256 * 528)
#define K3_ROFF  (K3_BOFF + 1024)
#define K3_SMEM  (K3_ROFF + 512)

__global__ __launch_bounds__(512, 1) void proj_v_mma(
        const float* __restrict__ Wv, const float* __restrict__ bv) {
    extern __shared__ char smem[];
    const uint32_t sbase = smem_u32(smem);
    const uint32_t wsm   = sbase + K3_WOFF;
    float* bsm = (float*)(smem + K3_BOFF);
    float* rsm = (float*)(smem + K3_ROFF);

    const int tid  = threadIdx.x;
    const int wid  = tid >> 5;
    const int lane = tid & 31;
    const int b    = blockIdx.y;
    const int m0   = blockIdx.x * 128;
    const int warp_m = wid & 3;
    const int warp_n = wid >> 2;
    const int lrow  = lane & 15;
    const int lcolB = (lane >> 4) * 16;

    const __nv_bfloat16* Xb = g_xh + (size_t)(b * N_ + m0) * C_;

#pragma unroll
    for (int t = 0; t < 2; t++) {
        int idx = tid + t * 512;
        int row = idx >> 3, c16 = idx & 7;
        CP_ASYNC16(sbase + row * 144 + c16 * 16, Xb + (size_t)row * C_ + c16 * 8);
    }
    CP_COMMIT();

#pragma unroll
    for (int t = 0; t < 32; t++) {
        int idx = tid + t * 512;
        int row = idx >> 6, q = idx & 63;
        float4 v = *(const float4*)&Wv[row * 256 + q * 4];
        __nv_bfloat162 p0, p1;
        p0.x = __float2bfloat16(v.x); p0.y = __float2bfloat16(v.y);
        p1.x = __float2bfloat16(v.z); p1.y = __float2bfloat16(v.w);
        *(__nv_bfloat162*)(smem + K3_WOFF + row * 528 + q * 8)     = p0;
        *(__nv_bfloat162*)(smem + K3_WOFF + row * 528 + q * 8 + 4) = p1;
    }
    if (tid < 256) bsm[tid] = bv[tid];
    if (tid < 128) rsm[tid] = g_R[b * N_ + m0 + tid] * VSC2;

    float acc[2][8][4];
#pragma unroll
    for (int mt = 0; mt < 2; mt++)
#pragma unroll
        for (int nt = 0; nt < 8; nt++)
#pragma unroll
            for (int r = 0; r < 4; r++) acc[mt][nt][r] = 0.0f;

    for (int kc = 0; kc < 4; kc++) {
        const int s = kc & 1;
        CP_WAIT0();
        __syncthreads();

        if (kc + 1 < 4) {
            const uint32_t sd = sbase + (s ^ 1) * 18432;
            const int k0n = (kc + 1) * 64;
#pragma unroll
            for (int t = 0; t < 2; t++) {
                int idx = tid + t * 512;
                int row = idx >> 3, c16 = idx & 7;
                CP_ASYNC16(sd + row * 144 + c16 * 16, Xb + (size_t)row * C_ + k0n + c16 * 8);
            }
            CP_COMMIT();
        }

        const uint32_t sa = sbase + s * 18432;
#pragma unroll
        for (int kk = 0; kk < 4; kk++) {
            uint32_t a[2][4];
#pragma unroll
            for (int mt = 0; mt < 2; mt++)
                LDMATRIX_X4(a[mt][0], a[mt][1], a[mt][2], a[mt][3],
                            sa + (warp_m * 32 + mt * 16 + lrow) * 144 + kk * 32 + lcolB);
            uint32_t br[4][4];
#pragma unroll
            for (int bt = 0; bt < 4; bt++)
                LDMATRIX_X4(br[bt][0], br[bt][1], br[bt][2], br[bt][3],
                            wsm + (warp_n * 64 + bt * 16 + lrow) * 528 + (kc * 64 + kk * 16) * 2 + lcolB);
#pragma unroll
            for (int mt = 0; mt < 2; mt++)
#pragma unroll
                for (int nt = 0; nt < 8; nt++) {
                    const int bt = nt >> 1, sel = nt & 1;
                    MMA_BF16(acc[mt][nt], a[mt], br[bt][sel], br[bt][sel + 2]);
                }
        }
    }

    // epilogue: (acc + bv[c]) * (VSC2/L[m]) -> s8, transpose to [c][m], store
    char* esp = smem;
#pragma unroll
    for (int h = 0; h < 2; h++) {
        __syncthreads();
        if ((warp_n >> 1) == h) {
            const int cbase = (warp_n & 1) * 64;
#pragma unroll
            for (int mt = 0; mt < 2; mt++) {
                const int m_l = warp_m * 32 + mt * 16 + (lane >> 2);
                const float r0 = rsm[m_l], r1 = rsm[m_l + 8];
#pragma unroll
                for (int nt = 0; nt < 8; nt++) {
                    const int c_l = cbase + nt * 8 + (lane & 3) * 2;
                    const float b0 = bsm[h * 128 + c_l], b1 = bsm[h * 128 + c_l + 1];
                    *(uint8_t*)(esp + c_l * 144 + m_l)           = (uint8_t)f_s8((acc[mt][nt][0] + b0) * r0);
                    *(uint8_t*)(esp + (c_l + 1) * 144 + m_l)     = (uint8_t)f_s8((acc[mt][nt][1] + b1) * r0);
                    *(uint8_t*)(esp + c_l * 144 + m_l + 8)       = (uint8_t)f_s8((acc[mt][nt][2] + b0) * r1);
                    *(uint8_t*)(esp + (c_l + 1) * 144 + m_l + 8) = (uint8_t)f_s8((acc[mt][nt][3] + b1) * r1);
                }
            }
        }
        __syncthreads();
#pragma unroll
        for (int t = 0; t < 2; t++) {
            int idx = tid + t * 512;
            int row = idx >> 3, q = idx & 7;
            float4 v = *(float4*)(esp + row * 144 + q * 16);
            *(float4*)&g_vs8[((size_t)(b * C_ + h * 128 + row)) * N_ + m0 + q * 16] = v;
        }
    }
}

// ---------------------------------------------------------------------------
// K4: out = E8 @ vs8^T via s8 IMMA (m16n8k32). Pure GEMM, R4-proven shape:
// CTA tile 128n x 256c, K=4096 in 32 chunks of 128 bytes, 2-stage, 512 thr.
// ---------------------------------------------------------------------------
#define O_ROWB  144
#define O_TILEA (128 * O_ROWB)
#define O_STG   (O_TILEA + 256 * O_ROWB)     // 55296
#define O_SMEM  (2 * O_STG)                  // 110592

__device__ __forceinline__ void o_load_chunk(uint32_t sbase, int stage,
                                             const uint8_t* Eb,
                                             const uint8_t* Vb,
                                             int m0, int tid) {
    uint32_t sa = sbase + stage * O_STG;
    uint32_t sb = sa + O_TILEA;
#pragma unroll
    for (int t = 0; t < 2; t++) {               // A: 128 rows x 128B
        int idx = tid + t * 512;
        int row = idx >> 3, c16 = idx & 7;
        CP_ASYNC16(sa + row * O_ROWB + c16 * 16, Eb + (size_t)row * N_ + m0 + c16 * 16);
    }
#pragma unroll
    for (int t = 0; t < 4; t++) {               // B: 256 rows x 128B
        int idx = tid + t * 512;
        int row = idx >> 3, c16 = idx & 7;
        CP_ASYNC16(sb + row * O_ROWB + c16 * 16, Vb + (size_t)row * N_ + m0 + c16 * 16);
    }
}

__global__ __launch_bounds__(512, 1) void attn_out_i8(const float* __restrict__ x,
                                                      const float* __restrict__ gamma,
                                                      float* __restrict__ out) {
    extern __shared__ char smem[];
    const uint32_t sbase = smem_u32(smem);

    const int tid  = threadIdx.x;
    const int wid  = tid >> 5;
    const int lane = tid & 31;
    const int b    = blockIdx.y;
    const int n0   = blockIdx.x * 128;

    const int warp_m = wid & 3;       // 32 n-rows
    const int warp_n = wid >> 2;      // 64 c-cols
    const int lrow  = lane & 15;
    const int lcolB = (lane >> 4) * 16;

    const uint8_t* Eb = g_E8 + (size_t)(b * N_ + n0) * N_;
    const uint8_t* Vb = g_vs8 + (size_t)b * C_ * N_;

    int acc[2][8][4];
#pragma unroll
    for (int mt = 0; mt < 2; mt++)
#pragma unroll
        for (int nt = 0; nt < 8; nt++)
#pragma unroll
            for (int r = 0; r < 4; r++) acc[mt][nt][r] = 0;

    o_load_chunk(sbase, 0, Eb, Vb, 0, tid);
    CP_COMMIT();

    for (int k = 0; k < 32; k++) {
        const int s = k & 1;
        CP_WAIT0();
        __syncthreads();

        if (k + 1 < 32) {
            o_load_chunk(sbase, s ^ 1, Eb, Vb, (k + 1) * 128, tid);
            CP_COMMIT();
        }

        const uint32_t sa = sbase + s * O_STG;
        const uint32_t sb = sa + O_TILEA;

#pragma unroll
        for (int kk = 0; kk < 4; kk++) {
            const int kb = kk * 32 + lcolB;
            uint32_t ae[2][4];
#pragma unroll
            for (int mt = 0; mt < 2; mt++)
                LDMATRIX_X4(ae[mt][0], ae[mt][1], ae[mt][2], ae[mt][3],
                            sa + (warp_m * 32 + mt * 16 + lrow) * O_ROWB + kb);
            uint32_t be[4][4];
#pragma unroll
            for (int bt = 0; bt < 4; bt++)
                LDMATRIX_X4(be[bt][0], be[bt][1], be[bt][2], be[bt][3],
                            sb + (warp_n * 64 + bt * 16 + lrow) * O_ROWB + kb);
#pragma unroll
            for (int mt = 0; mt < 2; mt++)
#pragma unroll
                for (int nt = 0; nt < 8; nt++) {
                    const int bt = nt >> 1, sel = nt & 1;
                    MMA_S8(acc[mt][nt], ae[mt], be[bt][sel], be[bt][sel + 2]);
                }
        }
    }

    // ---------------- epilogue: dequant + two c-halves transpose via smem
    const float g = __ldg(gamma) * (1.0f / (ESC * VSC2));
    float* so = (float*)smem;                 // [128 c][132 n] fp32

#pragma unroll
    for (int h = 0; h < 2; h++) {
        __syncthreads();
        if ((warp_n >> 1) == h) {
            const int cbase = (warp_n & 1) * 64;
#pragma unroll
            for (int mt = 0; mt < 2; mt++) {
                const int n_l = warp_m * 32 + mt * 16 + (lane >> 2);
#pragma unroll
                for (int nt = 0; nt < 8; nt++) {
                    const int c_l = cbase + nt * 8 + (lane & 3) * 2;
                    so[c_l * 132 + n_l]           = (float)acc[mt][nt][0];
                    so[(c_l + 1) * 132 + n_l]     = (float)acc[mt][nt][1];
                    so[c_l * 132 + n_l + 8]       = (float)acc[mt][nt][2];
                    so[(c_l + 1) * 132 + n_l + 8] = (float)acc[mt][nt][3];
                }
            }
        }
        __syncthreads();
#pragma unroll
        for (int t = 0; t < 8; t++) {
            int idx = tid + t * 512;
            int c_l = idx >> 5, q = idx & 31;
            float4 v = *(float4*)&so[c_l * 132 + q * 4];
            size_t gi = ((size_t)(b * C_ + h * 128 + c_l)) * N_ + n0 + q * 4;
            float4 xv = *(const float4*)&x[gi];
            float4 o;
            o.x = g * v.x + xv.x;
            o.y = g * v.y + xv.y;
            o.z = g * v.z + xv.z;
            o.w = g * v.w + xv.w;
            *(float4*)&out[gi] = o;
        }
    }
}

// ---------------------------------------------------------------------------
extern "C" void kernel_launch(void* const* d_in, const int* in_sizes, int n_in,
                              void* d_out, int out_size) {
    const float* x     = (const float*)d_in[0];
    const float* Wq    = (const float*)d_in[1];
    const float* bq    = (const float*)d_in[2];
    const float* Wk    = (const float*)d_in[3];
    const float* bk    = (const float*)d_in[4];
    const float* Wv    = (const float*)d_in[5];
    const float* bv    = (const float*)d_in[6];
    const float* gamma = (const float*)d_in[7];
    float* out = (float*)d_out;

    cudaFuncSetAttribute(proj_qk_mma, cudaFuncAttributeMaxDynamicSharedMemorySize, K1_SMEM);
    cudaFuncSetAttribute(proj_v_mma,  cudaFuncAttributeMaxDynamicSharedMemorySize, K3_SMEM);
    cudaFuncSetAttribute(attn_out_i8, cudaFuncAttributeMaxDynamicSharedMemorySize, O_SMEM);

    xpose_kernel<<<dim3(N_ / 64, C_ / 64, B_), 256>>>(x);
    proj_qk_mma<<<dim3(N_ / 128, B_), 256, K1_SMEM>>>(Wq, bq, Wk, bk);
    stats_i8<<<dim3(N_ / 64, B_), 256>>>();
    proj_v_mma<<<dim3(N_ / 128, B_), 512, K3_SMEM>>>(Wv, bv);
    attn_out_i8<<<dim3(N_ / 128, B_), 512, O_SMEM>>>(x, gamma, out);
}

// round 16
// speedup vs baseline: 1.8144x; 1.8144x over previous
#include <cuda_runtime.h>
#include <cuda_bf16.h>
#include <cstdint>

#define B_  4
#define C_  256
#define N_  4096

// ---------------------------------------------------------------------------
// Scratch (__device__ globals; allocation-free rule)
// ---------------------------------------------------------------------------
__device__ __align__(16) __nv_bfloat16  g_xh[(size_t)B_ * N_ * C_];   // [b][n][c] bf16 (8MB)
__device__ __align__(16) __nv_bfloat16  g_qkh[B_ * N_ * 64];          // [b][n][q|k] bf16 (2MB)
__device__ __align__(16) __nv_bfloat16  g_vs[(size_t)B_ * C_ * N_];   // [b][c][m] bf16 * 1/L (8MB)
__device__ float                        g_R[B_ * N_];                 // 1/L[m]

// ---------------------------------------------------------------------------
// PTX helpers (base sm_80+ ISA only — harness targets plain sm_103)
// ---------------------------------------------------------------------------
__device__ __forceinline__ uint32_t smem_u32(const void* p) {
    uint32_t a;
    asm("{ .reg .u64 t; cvta.to.shared.u64 t, %1; cvt.u32.u64 %0, t; }" : "=r"(a) : "l"(p));
    return a;
}
#define CP_ASYNC16(dst, src) \
    asm volatile("cp.async.cg.shared.global [%0], [%1], 16;" :: "r"(dst), "l"(src))
#define CP_COMMIT()  asm volatile("cp.async.commit_group;" ::: "memory")
#define CP_WAIT0()   asm volatile("cp.async.wait_group 0;" ::: "memory")
#define CP_WAIT1()   asm volatile("cp.async.wait_group 1;" ::: "memory")

#define LDMATRIX_X4(r0, r1, r2, r3, addr) \
    asm volatile("ldmatrix.sync.aligned.m8n8.x4.shared.b16 {%0,%1,%2,%3}, [%4];" \
                 : "=r"(r0), "=r"(r1), "=r"(r2), "=r"(r3) : "r"(addr))

#define MMA_BF16(d, a, b0v, b1v) \
    asm volatile("mma.sync.aligned.m16n8k16.row.col.f32.bf16.bf16.f32 " \
                 "{%0,%1,%2,%3}, {%4,%5,%6,%7}, {%8,%9}, {%0,%1,%2,%3};" \
                 : "+f"((d)[0]), "+f"((d)[1]), "+f"((d)[2]), "+f"((d)[3]) \
                 : "r"((a)[0]), "r"((a)[1]), "r"((a)[2]), "r"((a)[3]), \
                   "r"(b0v), "r"(b1v))

// ---------------------------------------------------------------------------
// K1: FUSED transpose + q/k projection. Writes g_xh (for K3) and g_qkh.
// grid (N/128, B) = 128 CTAs, 256 threads.
// smem: xb f32 [64][132] @0 (33792) | X bf16 [128 rows x 528B] @33792 (67584)
//       | W bf16 [64][528] @101376 (33792) | bias @135168 -> 135424 total
// ---------------------------------------------------------------------------
#define Q_XBOFF 0
#define Q_XOFF  33792
#define Q_WOFF  (Q_XOFF + 67584)
#define Q_BOFF  (Q_WOFF + 64 * 528)
#define Q_SMEM  (Q_BOFF + 256)

__global__ __launch_bounds__(256, 1) void proj_qk_fused(
        const float* __restrict__ x,
        const float* __restrict__ Wq, const float* __restrict__ bq,
        const float* __restrict__ Wk, const float* __restrict__ bk) {
    extern __shared__ char smem[];
    const uint32_t sbase = smem_u32(smem);
    float* xb  = (float*)(smem + Q_XBOFF);
    float* bsm = (float*)(smem + Q_BOFF);
    const uint32_t Xs = sbase + Q_XOFF;
    const uint32_t Ws = sbase + Q_WOFF;

    const int tid  = threadIdx.x;
    const int wid  = tid >> 5;
    const int lane = tid & 31;
    const int b    = blockIdx.y;
    const int n0   = blockIdx.x * 128;
    const int lrow  = lane & 15;
    const int lcolB = (lane >> 4) * 16;

    // W -> bf16 smem, bias
#pragma unroll
    for (int t = 0; t < 64; t++) {
        int idx = tid + t * 256;
        int co = idx >> 8, c = idx & 255;
        float v = (co < 32) ? Wq[co * 256 + c] : Wk[(co - 32) * 256 + c];
        *(__nv_bfloat16*)(smem + Q_WOFF + co * 528 + c * 2) = __float2bfloat16(v);
    }
    if (tid < 64) bsm[tid] = (tid < 32) ? bq[tid] : bk[tid - 32];

    // transpose x[256c x 128n] -> X smem bf16 [128n][256c] AND g_xh
#pragma unroll
    for (int cb = 0; cb < 4; cb++) {
        __syncthreads();
#pragma unroll
        for (int t = 0; t < 8; t++) {
            int idx = tid + t * 256;
            int cc = idx >> 5, q = idx & 31;
            *(float4*)&xb[cc * 132 + q * 4] =
                *(const float4*)&x[((size_t)(b * C_ + cb * 64 + cc)) * N_ + n0 + q * 4];
        }
        __syncthreads();
#pragma unroll
        for (int t = 0; t < 16; t++) {
            int idx = tid + t * 256;
            int nl = idx >> 5, pr = idx & 31;
            __nv_bfloat162 p;
            p.x = __float2bfloat16(xb[(2 * pr) * 132 + nl]);
            p.y = __float2bfloat16(xb[(2 * pr + 1) * 132 + nl]);
            *(__nv_bfloat162*)(smem + Q_XOFF + nl * 528 + (cb * 64 + 2 * pr) * 2) = p;
            *(__nv_bfloat162*)&g_xh[((size_t)(b * N_ + n0 + nl)) * C_ + cb * 64 + 2 * pr] = p;
        }
    }
    __syncthreads();

    // MMA: qk[128n x 64co] = X[128n x 256c] @ W[64co x 256c]^T
    float acc[8][4];
#pragma unroll
    for (int nt = 0; nt < 8; nt++)
#pragma unroll
        for (int r = 0; r < 4; r++) acc[nt][r] = 0.0f;

#pragma unroll
    for (int kk = 0; kk < 16; kk++) {
        uint32_t a[4];
        LDMATRIX_X4(a[0], a[1], a[2], a[3],
                    Xs + (wid * 16 + lrow) * 528 + kk * 32 + lcolB);
        uint32_t br[4][4];
#pragma unroll
        for (int bt = 0; bt < 4; bt++)
            LDMATRIX_X4(br[bt][0], br[bt][1], br[bt][2], br[bt][3],
                        Ws + (bt * 16 + lrow) * 528 + kk * 32 + lcolB);
#pragma unroll
        for (int nt = 0; nt < 8; nt++) {
            const int bt = nt >> 1, sel = nt & 1;
            MMA_BF16(acc[nt], a, br[bt][sel], br[bt][sel + 2]);
        }
    }

    const int nrow = n0 + wid * 16 + (lane >> 2);
#pragma unroll
    for (int nt = 0; nt < 8; nt++) {
        const int co = nt * 8 + (lane & 3) * 2;
        const float b0 = bsm[co], b1 = bsm[co + 1];
        __nv_bfloat162 p0, p1;
        p0.x = __float2bfloat16(acc[nt][0] + b0);
        p0.y = __float2bfloat16(acc[nt][1] + b1);
        p1.x = __float2bfloat16(acc[nt][2] + b0);
        p1.y = __float2bfloat16(acc[nt][3] + b1);
        *(__nv_bfloat162*)&g_qkh[((size_t)(b * N_ + nrow)) * 64 + co]     = p0;
        *(__nv_bfloat162*)&g_qkh[((size_t)(b * N_ + nrow + 8)) * 64 + co] = p1;
    }
}

// ---------------------------------------------------------------------------
// K2: L-sum only; exp on MUFU (R7 version, unchanged)
// ---------------------------------------------------------------------------
__global__ __launch_bounds__(256, 2) void lsum_mma() {
    __shared__ __align__(16) char ksm_s[64 * 80];
    __shared__ __align__(16) char qsm_s[2 * 128 * 80];
    __shared__ float redsm[8 * 64];
    const uint32_t ksm = smem_u32(ksm_s);
    const uint32_t qsm = smem_u32(qsm_s);

    const int tid  = threadIdx.x;
    const int wid  = tid >> 5;
    const int lane = tid & 31;
    const int b    = blockIdx.y;
    const int m0   = blockIdx.x * 64;
    const int lrow  = lane & 15;
    const int lcolB = (lane >> 4) * 16;

    const __nv_bfloat16* QK = g_qkh + (size_t)b * N_ * 64;

    {
        int row = tid >> 2, c16 = tid & 3;
        CP_ASYNC16(ksm + row * 80 + c16 * 16, QK + (size_t)(m0 + row) * 64 + 32 + c16 * 8);
    }
#pragma unroll
    for (int t = 0; t < 2; t++) {
        int idx = tid + t * 256;
        int row = idx >> 2, c16 = idx & 3;
        CP_ASYNC16(qsm + row * 80 + c16 * 16, QK + (size_t)row * 64 + c16 * 8);
    }
    CP_COMMIT();

    float csum[8][2];
#pragma unroll
    for (int u = 0; u < 8; u++) { csum[u][0] = 0.0f; csum[u][1] = 0.0f; }

    for (int nt = 0; nt < 32; nt++) {
        const int s = nt & 1;
        CP_WAIT0();
        __syncthreads();

        if (nt + 1 < 32) {
            const int n0n = (nt + 1) * 128;
            const uint32_t qd = qsm + (s ^ 1) * 10240;
#pragma unroll
            for (int t = 0; t < 2; t++) {
                int idx = tid + t * 256;
                int row = idx >> 2, c16 = idx & 3;
                CP_ASYNC16(qd + row * 80 + c16 * 16, QK + (size_t)(n0n + row) * 64 + c16 * 8);
            }
            CP_COMMIT();
        }

        const uint32_t qs = qsm + s * 10240;

        float acc[8][4];
#pragma unroll
        for (int u = 0; u < 8; u++)
#pragma unroll
            for (int r = 0; r < 4; r++) acc[u][r] = 0.0f;

#pragma unroll
        for (int kk = 0; kk < 2; kk++) {
            const int kb = kk * 32 + lcolB;
            uint32_t a[4];
            LDMATRIX_X4(a[0], a[1], a[2], a[3], qs + (wid * 16 + lrow) * 80 + kb);
            uint32_t br[4][4];
#pragma unroll
            for (int bt = 0; bt < 4; bt++)
                LDMATRIX_X4(br[bt][0], br[bt][1], br[bt][2], br[bt][3],
                            ksm + (bt * 16 + lrow) * 80 + kb);
#pragma unroll
            for (int u = 0; u < 8; u++) {
                const int bt = u >> 1, sel = u & 1;
                MMA_BF16(acc[u], a, br[bt][sel], br[bt][sel + 2]);
            }
        }

#pragma unroll
        for (int u = 0; u < 8; u++) {
            csum[u][0] += __expf(acc[u][0]) + __expf(acc[u][2]);
            csum[u][1] += __expf(acc[u][1]) + __expf(acc[u][3]);
        }
    }

#pragma unroll
    for (int off = 16; off >= 4; off >>= 1)
#pragma unroll
        for (int u = 0; u < 8; u++) {
            csum[u][0] += __shfl_down_sync(0xffffffffu, csum[u][0], off);
            csum[u][1] += __shfl_down_sync(0xffffffffu, csum[u][1], off);
        }
    if (lane < 4) {
#pragma unroll
        for (int u = 0; u < 8; u++) {
            redsm[wid * 64 + u * 8 + lane * 2 + 0] = csum[u][0];
            redsm[wid * 64 + u * 8 + lane * 2 + 1] = csum[u][1];
        }
    }
    __syncthreads();
    if (tid < 64) {
        float L = 0.0f;
#pragma unroll
        for (int w = 0; w < 8; w++) L += redsm[w * 64 + tid];
        g_R[b * N_ + m0 + tid] = 1.0f / L;
    }
}

// ---------------------------------------------------------------------------
// K3: v projection via HMMA + bias, * 1/L, stored TRANSPOSED bf16 (R7 ver.)
// ---------------------------------------------------------------------------
#define K3_WOFF  36864
#define K3_BOFF  (K3_WOFF + 256 * 528)
#define K3_ROFF  (K3_BOFF + 1024)
#define K3_SMEM  (K3_ROFF + 512)

__global__ __launch_bounds__(512, 1) void proj_v_mma(
        const float* __restrict__ Wv, const float* __restrict__ bv) {
    extern __shared__ char smem[];
    const uint32_t sbase = smem_u32(smem);
    const uint32_t wsm   = sbase + K3_WOFF;
    float* bsm = (float*)(smem + K3_BOFF);
    float* rsm = (float*)(smem + K3_ROFF);

    const int tid  = threadIdx.x;
    const int wid  = tid >> 5;
    const int lane = tid & 31;
    const int b    = blockIdx.y;
    const int m0   = blockIdx.x * 128;
    const int warp_m = wid & 3;
    const int warp_n = wid >> 2;
    const int lrow  = lane & 15;
    const int lcolB = (lane >> 4) * 16;

    const __nv_bfloat16* Xb = g_xh + (size_t)(b * N_ + m0) * C_;

#pragma unroll
    for (int t = 0; t < 2; t++) {
        int idx = tid + t * 512;
        int row = idx >> 3, c16 = idx & 7;
        CP_ASYNC16(sbase + row * 144 + c16 * 16, Xb + (size_t)row * C_ + c16 * 8);
    }
    CP_COMMIT();

#pragma unroll
    for (int t = 0; t < 32; t++) {
        int idx = tid + t * 512;
        int row = idx >> 6, q = idx & 63;
        float4 v = *(const float4*)&Wv[row * 256 + q * 4];
        __nv_bfloat162 p0, p1;
        p0.x = __float2bfloat16(v.x); p0.y = __float2bfloat16(v.y);
        p1.x = __float2bfloat16(v.z); p1.y = __float2bfloat16(v.w);
        *(__nv_bfloat162*)(smem + K3_WOFF + row * 528 + q * 8)     = p0;
        *(__nv_bfloat162*)(smem + K3_WOFF + row * 528 + q * 8 + 4) = p1;
    }
    if (tid < 256) bsm[tid] = bv[tid];
    if (tid < 128) rsm[tid] = g_R[b * N_ + m0 + tid];

    float acc[2][8][4];
#pragma unroll
    for (int mt = 0; mt < 2; mt++)
#pragma unroll
        for (int nt = 0; nt < 8; nt++)
#pragma unroll
            for (int r = 0; r < 4; r++) acc[mt][nt][r] = 0.0f;

    for (int kc = 0; kc < 4; kc++) {
        const int s = kc & 1;
        CP_WAIT0();
        __syncthreads();

        if (kc + 1 < 4) {
            const uint32_t sd = sbase + (s ^ 1) * 18432;
            const int k0n = (kc + 1) * 64;
#pragma unroll
            for (int t = 0; t < 2; t++) {
                int idx = tid + t * 512;
                int row = idx >> 3, c16 = idx & 7;
                CP_ASYNC16(sd + row * 144 + c16 * 16, Xb + (size_t)row * C_ + k0n + c16 * 8);
            }
            CP_COMMIT();
        }

        const uint32_t sa = sbase + s * 18432;
#pragma unroll
        for (int kk = 0; kk < 4; kk++) {
            uint32_t a[2][4];
#pragma unroll
            for (int mt = 0; mt < 2; mt++)
                LDMATRIX_X4(a[mt][0], a[mt][1], a[mt][2], a[mt][3],
                            sa + (warp_m * 32 + mt * 16 + lrow) * 144 + kk * 32 + lcolB);
            uint32_t br[4][4];
#pragma unroll
            for (int bt = 0; bt < 4; bt++)
                LDMATRIX_X4(br[bt][0], br[bt][1], br[bt][2], br[bt][3],
                            wsm + (warp_n * 64 + bt * 16 + lrow) * 528 + (kc * 64 + kk * 16) * 2 + lcolB);
#pragma unroll
            for (int mt = 0; mt < 2; mt++)
#pragma unroll
                for (int nt = 0; nt < 8; nt++) {
                    const int bt = nt >> 1, sel = nt & 1;
                    MMA_BF16(acc[mt][nt], a[mt], br[bt][sel], br[bt][sel + 2]);
                }
        }
    }

    char* esp = smem;
#pragma unroll
    for (int h = 0; h < 2; h++) {
        __syncthreads();
        if ((warp_n >> 1) == h) {
            const int cbase = (warp_n & 1) * 64;
#pragma unroll
            for (int mt = 0; mt < 2; mt++) {
                const int m_l = warp_m * 32 + mt * 16 + (lane >> 2);
                const float r0 = rsm[m_l], r1 = rsm[m_l + 8];
#pragma unroll
                for (int nt = 0; nt < 8; nt++) {
                    const int c_l = cbase + nt * 8 + (lane & 3) * 2;
                    const float b0 = bsm[h * 128 + c_l], b1 = bsm[h * 128 + c_l + 1];
                    *(__nv_bfloat16*)(esp + c_l * 272 + m_l * 2)             = __float2bfloat16((acc[mt][nt][0] + b0) * r0);
                    *(__nv_bfloat16*)(esp + (c_l + 1) * 272 + m_l * 2)       = __float2bfloat16((acc[mt][nt][1] + b1) * r0);
                    *(__nv_bfloat16*)(esp + c_l * 272 + (m_l + 8) * 2)       = __float2bfloat16((acc[mt][nt][2] + b0) * r1);
                    *(__nv_bfloat16*)(esp + (c_l + 1) * 272 + (m_l + 8) * 2) = __float2bfloat16((acc[mt][nt][3] + b1) * r1);
                }
            }
        }
        __syncthreads();
#pragma unroll
        for (int t = 0; t < 4; t++) {
            int idx = tid + t * 512;
            int row = idx >> 4, q = idx & 15;
            float4 v = *(float4*)(esp + row * 272 + q * 16);
            *(float4*)&g_vs[((size_t)(b * C_ + h * 128 + row)) * N_ + m0 + q * 8] = v;
        }
    }
}

// ---------------------------------------------------------------------------
// K4: FUSED attention output (bf16), single barrier/chunk pipeline,
// all buffers double-buffered, 2 CTAs/SM.
// Per CTA: 64 n-rows x full C=256; 64 m-chunks of 64.
// smem: q [64x80] @0 | k 2st [64x80] @5120 | vs 2st [256x144] @15360 |
//       esm 2st [64x144] @89088  -> 107520 B  (2 CTA/SM: 215040 <= 227KB)
// ---------------------------------------------------------------------------
#define F_QOFF   0
#define F_KOFF   5120
#define F_KSTG   5120
#define F_VOFF   15360
#define F_VSTG   36864
#define F_EOFF   89088
#define F_ESTG   9216
#define F_SMEM   107520

__device__ __forceinline__ void f_load_k(uint32_t sbase, int st,
                                         const __nv_bfloat16* QK, int m0, int tid) {
    uint32_t ks = sbase + F_KOFF + st * F_KSTG;
    int row = tid >> 2, c16 = tid & 3;
    CP_ASYNC16(ks + row * 80 + c16 * 16, QK + (size_t)(m0 + row) * 64 + 32 + c16 * 8);
}
__device__ __forceinline__ void f_load_v(uint32_t sbase, int st,
                                         const __nv_bfloat16* Vb, int m0, int tid) {
    uint32_t vs = sbase + F_VOFF + st * F_VSTG;
#pragma unroll
    for (int t = 0; t < 8; t++) {
        int idx = tid + t * 256;
        int row = idx >> 3, c16 = idx & 7;
        CP_ASYNC16(vs + row * 144 + c16 * 16, Vb + (size_t)row * N_ + m0 + c16 * 8);
    }
}

// S = q k^T (bf16) -> exp (MUFU) -> esm[ebuf] (bf16)
__device__ __forceinline__ void f_s_phase(uint32_t sbase, char* smem, int kst, int ebuf,
                                          int warp_m, int warp_g, int lane,
                                          int lrow, int lcolB) {
    const uint32_t ks = sbase + F_KOFF + kst * F_KSTG;
    char* esp = smem + F_EOFF + ebuf * F_ESTG;

    float accs[2][2][4];
#pragma unroll
    for (int mt = 0; mt < 2; mt++)
#pragma unroll
        for (int u = 0; u < 2; u++)
#pragma unroll
            for (int r = 0; r < 4; r++) accs[mt][u][r] = 0.0f;

#pragma unroll
    for (int kk = 0; kk < 2; kk++) {
        const int kb = kk * 32 + lcolB;
        uint32_t a[2][4];
#pragma unroll
        for (int mt = 0; mt < 2; mt++)
            LDMATRIX_X4(a[mt][0], a[mt][1], a[mt][2], a[mt][3],
                        sbase + F_QOFF + (warp_m * 32 + mt * 16 + lrow) * 80 + kb);
        uint32_t bf[4];
        LDMATRIX_X4(bf[0], bf[1], bf[2], bf[3],
                    ks + (warp_g * 16 + lrow) * 80 + kb);
#pragma unroll
        for (int mt = 0; mt < 2; mt++)
#pragma unroll
            for (int u = 0; u < 2; u++)
                MMA_BF16(accs[mt][u], a[mt], bf[u], bf[u + 2]);
    }

#pragma unroll
    for (int mt = 0; mt < 2; mt++) {
        const int row = warp_m * 32 + mt * 16 + (lane >> 2);
#pragma unroll
        for (int u = 0; u < 2; u++) {
            const int col = warp_g * 16 + u * 8 + (lane & 3) * 2;
            float e0 = __expf(accs[mt][u][0]);
            float e1 = __expf(accs[mt][u][1]);
            float e2 = __expf(accs[mt][u][2]);
            float e3 = __expf(accs[mt][u][3]);
            __nv_bfloat162 p01, p23;
            p01.x = __float2bfloat16(e0); p01.y = __float2bfloat16(e1);
            p23.x = __float2bfloat16(e2); p23.y = __float2bfloat16(e3);
            *(__nv_bfloat162*)(esp + row * 144 + col * 2)       = p01;
            *(__nv_bfloat162*)(esp + (row + 8) * 144 + col * 2) = p23;
        }
    }
}

// out += esm[ebuf](64n x 64m) @ vs[vst](256c x 64m)^T
__device__ __forceinline__ void f_out_phase(uint32_t sbase, int vst, int ebuf,
                                            float acco[2][8][4],
                                            int warp_m, int warp_g,
                                            int lrow, int lcolB) {
    const uint32_t vsm = sbase + F_VOFF + vst * F_VSTG;
    const uint32_t esm = sbase + F_EOFF + ebuf * F_ESTG;
#pragma unroll
    for (int kk = 0; kk < 4; kk++) {
        const int kb = kk * 32 + lcolB;
        uint32_t ae[2][4];
#pragma unroll
        for (int mt = 0; mt < 2; mt++)
            LDMATRIX_X4(ae[mt][0], ae[mt][1], ae[mt][2], ae[mt][3],
                        esm + (warp_m * 32 + mt * 16 + lrow) * 144 + kb);
        uint32_t be[4][4];
#pragma unroll
        for (int bt = 0; bt < 4; bt++)
            LDMATRIX_X4(be[bt][0], be[bt][1], be[bt][2], be[bt][3],
                        vsm + (warp_g * 64 + bt * 16 + lrow) * 144 + kb);
#pragma unroll
        for (int mt = 0; mt < 2; mt++)
#pragma unroll
            for (int nt = 0; nt < 8; nt++) {
                const int bt = nt >> 1, sel = nt & 1;
                MMA_BF16(acco[mt][nt], ae[mt], be[bt][sel], be[bt][sel + 2]);
            }
    }
}

__global__ __launch_bounds__(256, 2) void attn_fused(const float* __restrict__ x,
                                                     const float* __restrict__ gamma,
                                                     float* __restrict__ out) {
    extern __shared__ char smem[];
    const uint32_t sbase = smem_u32(smem);

    const int tid  = threadIdx.x;
    const int wid  = tid >> 5;
    const int lane = tid & 31;
    const int b    = blockIdx.y;
    const int n0   = blockIdx.x * 64;
    const int warp_m = wid & 1;      // 32 n-rows
    const int warp_g = wid >> 1;     // 0..3
    const int lrow  = lane & 15;
    const int lcolB = (lane >> 4) * 16;

    const __nv_bfloat16* QK = g_qkh + (size_t)b * N_ * 64;
    const __nv_bfloat16* Vb = g_vs + (size_t)b * C_ * N_;

    // prologue: P0 = [q, k(0), vs(0)], P1 = [k(1)]
    {
        int row = tid >> 2, c16 = tid & 3;
        CP_ASYNC16(sbase + F_QOFF + row * 80 + c16 * 16, QK + (size_t)(n0 + row) * 64 + c16 * 8);
    }
    f_load_k(sbase, 0, QK, 0, tid);
    f_load_v(sbase, 0, Vb, 0, tid);
    CP_COMMIT();
    f_load_k(sbase, 1, QK, 64, tid);
    CP_COMMIT();

    float acco[2][8][4];
#pragma unroll
    for (int mt = 0; mt < 2; mt++)
#pragma unroll
        for (int nt = 0; nt < 8; nt++)
#pragma unroll
            for (int r = 0; r < 4; r++) acco[mt][nt][r] = 0.0f;

    CP_WAIT1();                 // P0 done: q, k(0), vs(0)
    __syncthreads();
    f_s_phase(sbase, smem, 0, 0, warp_m, warp_g, lane, lrow, lcolB);   // S(0) -> esm0

    for (int mc = 0; mc < 64; mc++) {
        CP_WAIT0();             // [k(mc+1), vs(mc)] landed
        __syncthreads();        // stage ownership + esm visibility

        // prefetch: k(mc+2) -> stage mc&1 (S(mc) done), vs(mc+1) -> stage (mc+1)&1
        bool cm = false;
        if (mc + 2 < 64) { f_load_k(sbase, mc & 1, QK, (mc + 2) * 64, tid); cm = true; }
        if (mc + 1 < 64) { f_load_v(sbase, (mc + 1) & 1, Vb, (mc + 1) * 64, tid); cm = true; }
        if (cm) CP_COMMIT();

        // out(mc): fills tensor pipe, no fresh deps
        f_out_phase(sbase, mc & 1, mc & 1, acco, warp_m, warp_g, lrow, lcolB);

        // S(mc+1) -> other esm buffer (k(mc+1) already resident)
        if (mc + 1 < 64)
            f_s_phase(sbase, smem, (mc + 1) & 1, (mc + 1) & 1,
                      warp_m, warp_g, lane, lrow, lcolB);
    }

    // ---------------- epilogue: two c-halves, transpose via smem
    const float g = __ldg(gamma);
    float* so = (float*)smem;                 // [128 c][68 n] fp32 = 34816 B

#pragma unroll
    for (int h = 0; h < 2; h++) {
        __syncthreads();
        if ((warp_g >> 1) == h) {
            const int cbase = (warp_g & 1) * 64;
#pragma unroll
            for (int mt = 0; mt < 2; mt++) {
                const int n_l = warp_m * 32 + mt * 16 + (lane >> 2);
#pragma unroll
                for (int nt = 0; nt < 8; nt++) {
                    const int c_l = cbase + nt * 8 + (lane & 3) * 2;
                    so[c_l * 68 + n_l]           = acco[mt][nt][0];
                    so[(c_l + 1) * 68 + n_l]     = acco[mt][nt][1];
                    so[c_l * 68 + n_l + 8]       = acco[mt][nt][2];
                    so[(c_l + 1) * 68 + n_l + 8] = acco[mt][nt][3];
                }
            }
        }
        __syncthreads();
#pragma unroll
        for (int t = 0; t < 8; t++) {
            int idx = tid + t * 256;
            int c_l = idx >> 4, q = idx & 15;
            float4 v = *(float4*)&so[c_l * 68 + q * 4];
            size_t gi = ((size_t)(b * C_ + h * 128 + c_l)) * N_ + n0 + q * 4;
            float4 xv = *(const float4*)&x[gi];
            float4 o;
            o.x = g * v.x + xv.x;
            o.y = g * v.y + xv.y;
            o.z = g * v.z + xv.z;
            o.w = g * v.w + xv.w;
            *(float4*)&out[gi] = o;
        }
    }
}

// ---------------------------------------------------------------------------
extern "C" void kernel_launch(void* const* d_in, const int* in_sizes, int n_in,
                              void* d_out, int out_size) {
    const float* x     = (const float*)d_in[0];
    const float* Wq    = (const float*)d_in[1];
    const float* bq    = (const float*)d_in[2];
    const float* Wk    = (const float*)d_in[3];
    const float* bk    = (const float*)d_in[4];
    const float* Wv    = (const float*)d_in[5];
    const float* bv    = (const float*)d_in[6];
    const float* gamma = (const float*)d_in[7];
    float* out = (float*)d_out;

    cudaFuncSetAttribute(proj_qk_fused, cudaFuncAttributeMaxDynamicSharedMemorySize, Q_SMEM);
    cudaFuncSetAttribute(proj_v_mma,    cudaFuncAttributeMaxDynamicSharedMemorySize, K3_SMEM);
    cudaFuncSetAttribute(attn_fused,    cudaFuncAttributeMaxDynamicSharedMemorySize, F_SMEM);

    proj_qk_fused<<<dim3(N_ / 128, B_), 256, Q_SMEM>>>(x, Wq, bq, Wk, bk);
    lsum_mma<<<dim3(N_ / 64, B_), 256>>>();
    proj_v_mma<<<dim3(N_ / 128, B_), 512, K3_SMEM>>>(Wv, bv);
    attn_fused<<<dim3(N_ / 64, B_), 256, F_SMEM>>>(x, gamma, out);
}

// round 17
// speedup vs baseline: 1.8237x; 1.0051x over previous
#include <cuda_runtime.h>
#include <cuda_bf16.h>
#include <cstdint>

#define B_  4
#define C_  256
#define N_  4096

// ---------------------------------------------------------------------------
// Scratch (__device__ globals; allocation-free rule)
// ---------------------------------------------------------------------------
__device__ __align__(16) __nv_bfloat16  g_xh[(size_t)B_ * N_ * C_];   // [b][n][c] bf16 (8MB)
__device__ __align__(16) __nv_bfloat16  g_qkh[B_ * N_ * 64];          // [b][n][q|k] bf16 (2MB)
__device__ __align__(16) __nv_bfloat16  g_vs[(size_t)B_ * C_ * N_];   // [b][c][m] bf16 * 1/L (8MB)
__device__ float                        g_R[B_ * N_];                 // 1/L[m]

// ---------------------------------------------------------------------------
// PTX helpers (base sm_80+ ISA only — harness targets plain sm_103)
// ---------------------------------------------------------------------------
__device__ __forceinline__ uint32_t smem_u32(const void* p) {
    uint32_t a;
    asm("{ .reg .u64 t; cvta.to.shared.u64 t, %1; cvt.u32.u64 %0, t; }" : "=r"(a) : "l"(p));
    return a;
}
#define CP_ASYNC16(dst, src) \
    asm volatile("cp.async.cg.shared.global [%0], [%1], 16;" :: "r"(dst), "l"(src))
#define CP_COMMIT()  asm volatile("cp.async.commit_group;" ::: "memory")
#define CP_WAIT0()   asm volatile("cp.async.wait_group 0;" ::: "memory")
#define CP_WAIT1()   asm volatile("cp.async.wait_group 1;" ::: "memory")

#define LDMATRIX_X4(r0, r1, r2, r3, addr) \
    asm volatile("ldmatrix.sync.aligned.m8n8.x4.shared.b16 {%0,%1,%2,%3}, [%4];" \
                 : "=r"(r0), "=r"(r1), "=r"(r2), "=r"(r3) : "r"(addr))

#define MMA_BF16(d, a, b0v, b1v) \
    asm volatile("mma.sync.aligned.m16n8k16.row.col.f32.bf16.bf16.f32 " \
                 "{%0,%1,%2,%3}, {%4,%5,%6,%7}, {%8,%9}, {%0,%1,%2,%3};" \
                 : "+f"((d)[0]), "+f"((d)[1]), "+f"((d)[2]), "+f"((d)[3]) \
                 : "r"((a)[0]), "r"((a)[1]), "r"((a)[2]), "r"((a)[3]), \
                   "r"(b0v), "r"(b1v))

// ---------------------------------------------------------------------------
// K1: FUSED transpose + q/k projection. Writes g_xh (for K3) and g_qkh.
// grid (N/128, B) = 128 CTAs, 256 threads.
// smem: xb f32 [64][132] @0 (33792) | X bf16 [128 rows x 528B] @33792 (67584)
//       | W bf16 [64][528] @101376 (33792) | bias @135168 -> 135424 total
// ---------------------------------------------------------------------------
#define Q_XBOFF 0
#define Q_XOFF  33792
#define Q_WOFF  (Q_XOFF + 67584)
#define Q_BOFF  (Q_WOFF + 64 * 528)
#define Q_SMEM  (Q_BOFF + 256)

__global__ __launch_bounds__(256, 1) void proj_qk_fused(
        const float* __restrict__ x,
        const float* __restrict__ Wq, const float* __restrict__ bq,
        const float* __restrict__ Wk, const float* __restrict__ bk) {
    extern __shared__ char smem[];
    const uint32_t sbase = smem_u32(smem);
    float* xb  = (float*)(smem + Q_XBOFF);
    float* bsm = (float*)(smem + Q_BOFF);
    const uint32_t Xs = sbase + Q_XOFF;
    const uint32_t Ws = sbase + Q_WOFF;

    const int tid  = threadIdx.x;
    const int wid  = tid >> 5;
    const int lane = tid & 31;
    const int b    = blockIdx.y;
    const int n0   = blockIdx.x * 128;
    const int lrow  = lane & 15;
    const int lcolB = (lane >> 4) * 16;

    // W -> bf16 smem, bias
#pragma unroll
    for (int t = 0; t < 64; t++) {
        int idx = tid + t * 256;
        int co = idx >> 8, c = idx & 255;
        float v = (co < 32) ? Wq[co * 256 + c] : Wk[(co - 32) * 256 + c];
        *(__nv_bfloat16*)(smem + Q_WOFF + co * 528 + c * 2) = __float2bfloat16(v);
    }
    if (tid < 64) bsm[tid] = (tid < 32) ? bq[tid] : bk[tid - 32];

    // transpose x[256c x 128n] -> X smem bf16 [128n][256c] AND g_xh
#pragma unroll
    for (int cb = 0; cb < 4; cb++) {
        __syncthreads();
#pragma unroll
        for (int t = 0; t < 8; t++) {
            int idx = tid + t * 256;
            int cc = idx >> 5, q = idx & 31;
            *(float4*)&xb[cc * 132 + q * 4] =
                *(const float4*)&x[((size_t)(b * C_ + cb * 64 + cc)) * N_ + n0 + q * 4];
        }
        __syncthreads();
#pragma unroll
        for (int t = 0; t < 16; t++) {
            int idx = tid + t * 256;
            int nl = idx >> 5, pr = idx & 31;
            __nv_bfloat162 p;
            p.x = __float2bfloat16(xb[(2 * pr) * 132 + nl]);
            p.y = __float2bfloat16(xb[(2 * pr + 1) * 132 + nl]);
            *(__nv_bfloat162*)(smem + Q_XOFF + nl * 528 + (cb * 64 + 2 * pr) * 2) = p;
            *(__nv_bfloat162*)&g_xh[((size_t)(b * N_ + n0 + nl)) * C_ + cb * 64 + 2 * pr] = p;
        }
    }
    __syncthreads();

    // MMA: qk[128n x 64co] = X[128n x 256c] @ W[64co x 256c]^T
    float acc[8][4];
#pragma unroll
    for (int nt = 0; nt < 8; nt++)
#pragma unroll
        for (int r = 0; r < 4; r++) acc[nt][r] = 0.0f;

#pragma unroll
    for (int kk = 0; kk < 16; kk++) {
        uint32_t a[4];
        LDMATRIX_X4(a[0], a[1], a[2], a[3],
                    Xs + (wid * 16 + lrow) * 528 + kk * 32 + lcolB);
        uint32_t br[4][4];
#pragma unroll
        for (int bt = 0; bt < 4; bt++)
            LDMATRIX_X4(br[bt][0], br[bt][1], br[bt][2], br[bt][3],
                        Ws + (bt * 16 + lrow) * 528 + kk * 32 + lcolB);
#pragma unroll
        for (int nt = 0; nt < 8; nt++) {
            const int bt = nt >> 1, sel = nt & 1;
            MMA_BF16(acc[nt], a, br[bt][sel], br[bt][sel + 2]);
        }
    }

    const int nrow = n0 + wid * 16 + (lane >> 2);
#pragma unroll
    for (int nt = 0; nt < 8; nt++) {
        const int co = nt * 8 + (lane & 3) * 2;
        const float b0 = bsm[co], b1 = bsm[co + 1];
        __nv_bfloat162 p0, p1;
        p0.x = __float2bfloat16(acc[nt][0] + b0);
        p0.y = __float2bfloat16(acc[nt][1] + b1);
        p1.x = __float2bfloat16(acc[nt][2] + b0);
        p1.y = __float2bfloat16(acc[nt][3] + b1);
        *(__nv_bfloat162*)&g_qkh[((size_t)(b * N_ + nrow)) * 64 + co]     = p0;
        *(__nv_bfloat162*)&g_qkh[((size_t)(b * N_ + nrow + 8)) * 64 + co] = p1;
    }
}

// ---------------------------------------------------------------------------
// K2: L-sum only; exp on MUFU (R7 version, unchanged)
// ---------------------------------------------------------------------------
__global__ __launch_bounds__(256, 2) void lsum_mma() {
    __shared__ __align__(16) char ksm_s[64 * 80];
    __shared__ __align__(16) char qsm_s[2 * 128 * 80];
    __shared__ float redsm[8 * 64];
    const uint32_t ksm = smem_u32(ksm_s);
    const uint32_t qsm = smem_u32(qsm_s);

    const int tid  = threadIdx.x;
    const int wid  = tid >> 5;
    const int lane = tid & 31;
    const int b    = blockIdx.y;
    const int m0   = blockIdx.x * 64;
    const int lrow  = lane & 15;
    const int lcolB = (lane >> 4) * 16;

    const __nv_bfloat16* QK = g_qkh + (size_t)b * N_ * 64;

    {
        int row = tid >> 2, c16 = tid & 3;
        CP_ASYNC16(ksm + row * 80 + c16 * 16, QK + (size_t)(m0 + row) * 64 + 32 + c16 * 8);
    }
#pragma unroll
    for (int t = 0; t < 2; t++) {
        int idx = tid + t * 256;
        int row = idx >> 2, c16 = idx & 3;
        CP_ASYNC16(qsm + row * 80 + c16 * 16, QK + (size_t)row * 64 + c16 * 8);
    }
    CP_COMMIT();

    float csum[8][2];
#pragma unroll
    for (int u = 0; u < 8; u++) { csum[u][0] = 0.0f; csum[u][1] = 0.0f; }

    for (int nt = 0; nt < 32; nt++) {
        const int s = nt & 1;
        CP_WAIT0();
        __syncthreads();

        if (nt + 1 < 32) {
            const int n0n = (nt + 1) * 128;
            const uint32_t qd = qsm + (s ^ 1) * 10240;
#pragma unroll
            for (int t = 0; t < 2; t++) {
                int idx = tid + t * 256;
                int row = idx >> 2, c16 = idx & 3;
                CP_ASYNC16(qd + row * 80 + c16 * 16, QK + (size_t)(n0n + row) * 64 + c16 * 8);
            }
            CP_COMMIT();
        }

        const uint32_t qs = qsm + s * 10240;

        float acc[8][4];
#pragma unroll
        for (int u = 0; u < 8; u++)
#pragma unroll
            for (int r = 0; r < 4; r++) acc[u][r] = 0.0f;

#pragma unroll
        for (int kk = 0; kk < 2; kk++) {
            const int kb = kk * 32 + lcolB;
            uint32_t a[4];
            LDMATRIX_X4(a[0], a[1], a[2], a[3], qs + (wid * 16 + lrow) * 80 + kb);
            uint32_t br[4][4];
#pragma unroll
            for (int bt = 0; bt < 4; bt++)
                LDMATRIX_X4(br[bt][0], br[bt][1], br[bt][2], br[bt][3],
                            ksm + (bt * 16 + lrow) * 80 + kb);
#pragma unroll
            for (int u = 0; u < 8; u++) {
                const int bt = u >> 1, sel = u & 1;
                MMA_BF16(acc[u], a, br[bt][sel], br[bt][sel + 2]);
            }
        }

#pragma unroll
        for (int u = 0; u < 8; u++) {
            csum[u][0] += __expf(acc[u][0]) + __expf(acc[u][2]);
            csum[u][1] += __expf(acc[u][1]) + __expf(acc[u][3]);
        }
    }

#pragma unroll
    for (int off = 16; off >= 4; off >>= 1)
#pragma unroll
        for (int u = 0; u < 8; u++) {
            csum[u][0] += __shfl_down_sync(0xffffffffu, csum[u][0], off);
            csum[u][1] += __shfl_down_sync(0xffffffffu, csum[u][1], off);
        }
    if (lane < 4) {
#pragma unroll
        for (int u = 0; u < 8; u++) {
            redsm[wid * 64 + u * 8 + lane * 2 + 0] = csum[u][0];
            redsm[wid * 64 + u * 8 + lane * 2 + 1] = csum[u][1];
        }
    }
    __syncthreads();
    if (tid < 64) {
        float L = 0.0f;
#pragma unroll
        for (int w = 0; w < 8; w++) L += redsm[w * 64 + tid];
        g_R[b * N_ + m0 + tid] = 1.0f / L;
    }
}

// ---------------------------------------------------------------------------
// K3: v projection via HMMA + bias, * 1/L, stored TRANSPOSED bf16 (R7 ver.)
// ---------------------------------------------------------------------------
#define K3_WOFF  36864
#define K3_BOFF  (K3_WOFF + 256 * 528)
#define K3_ROFF  (K3_BOFF + 1024)
#define K3_SMEM  (K3_ROFF + 512)

__global__ __launch_bounds__(512, 1) void proj_v_mma(
        const float* __restrict__ Wv, const float* __restrict__ bv) {
    extern __shared__ char smem[];
    const uint32_t sbase = smem_u32(smem);
    const uint32_t wsm   = sbase + K3_WOFF;
    float* bsm = (float*)(smem + K3_BOFF);
    float* rsm = (float*)(smem + K3_ROFF);

    const int tid  = threadIdx.x;
    const int wid  = tid >> 5;
    const int lane = tid & 31;
    const int b    = blockIdx.y;
    const int m0   = blockIdx.x * 128;
    const int warp_m = wid & 3;
    const int warp_n = wid >> 2;
    const int lrow  = lane & 15;
    const int lcolB = (lane >> 4) * 16;

    const __nv_bfloat16* Xb = g_xh + (size_t)(b * N_ + m0) * C_;

#pragma unroll
    for (int t = 0; t < 2; t++) {
        int idx = tid + t * 512;
        int row = idx >> 3, c16 = idx & 7;
        CP_ASYNC16(sbase + row * 144 + c16 * 16, Xb + (size_t)row * C_ + c16 * 8);
    }
    CP_COMMIT();

#pragma unroll
    for (int t = 0; t < 32; t++) {
        int idx = tid + t * 512;
        int row = idx >> 6, q = idx & 63;
        float4 v = *(const float4*)&Wv[row * 256 + q * 4];
        __nv_bfloat162 p0, p1;
        p0.x = __float2bfloat16(v.x); p0.y = __float2bfloat16(v.y);
        p1.x = __float2bfloat16(v.z); p1.y = __float2bfloat16(v.w);
        *(__nv_bfloat162*)(smem + K3_WOFF + row * 528 + q * 8)     = p0;
        *(__nv_bfloat162*)(smem + K3_WOFF + row * 528 + q * 8 + 4) = p1;
    }
    if (tid < 256) bsm[tid] = bv[tid];
    if (tid < 128) rsm[tid] = g_R[b * N_ + m0 + tid];

    float acc[2][8][4];
#pragma unroll
    for (int mt = 0; mt < 2; mt++)
#pragma unroll
        for (int nt = 0; nt < 8; nt++)
#pragma unroll
            for (int r = 0; r < 4; r++) acc[mt][nt][r] = 0.0f;

    for (int kc = 0; kc < 4; kc++) {
        const int s = kc & 1;
        CP_WAIT0();
        __syncthreads();

        if (kc + 1 < 4) {
            const uint32_t sd = sbase + (s ^ 1) * 18432;
            const int k0n = (kc + 1) * 64;
#pragma unroll
            for (int t = 0; t < 2; t++) {
                int idx = tid + t * 512;
                int row = idx >> 3, c16 = idx & 7;
                CP_ASYNC16(sd + row * 144 + c16 * 16, Xb + (size_t)row * C_ + k0n + c16 * 8);
            }
            CP_COMMIT();
        }

        const uint32_t sa = sbase + s * 18432;
#pragma unroll
        for (int kk = 0; kk < 4; kk++) {
            uint32_t a[2][4];
#pragma unroll
            for (int mt = 0; mt < 2; mt++)
                LDMATRIX_X4(a[mt][0], a[mt][1], a[mt][2], a[mt][3],
                            sa + (warp_m * 32 + mt * 16 + lrow) * 144 + kk * 32 + lcolB);
            uint32_t br[4][4];
#pragma unroll
            for (int bt = 0; bt < 4; bt++)
                LDMATRIX_X4(br[bt][0], br[bt][1], br[bt][2], br[bt][3],
                            wsm + (warp_n * 64 + bt * 16 + lrow) * 528 + (kc * 64 + kk * 16) * 2 + lcolB);
#pragma unroll
            for (int mt = 0; mt < 2; mt++)
#pragma unroll
                for (int nt = 0; nt < 8; nt++) {
                    const int bt = nt >> 1, sel = nt & 1;
                    MMA_BF16(acc[mt][nt], a[mt], br[bt][sel], br[bt][sel + 2]);
                }
        }
    }

    char* esp = smem;
#pragma unroll
    for (int h = 0; h < 2; h++) {
        __syncthreads();
        if ((warp_n >> 1) == h) {
            const int cbase = (warp_n & 1) * 64;
#pragma unroll
            for (int mt = 0; mt < 2; mt++) {
                const int m_l = warp_m * 32 + mt * 16 + (lane >> 2);
                const float r0 = rsm[m_l], r1 = rsm[m_l + 8];
#pragma unroll
                for (int nt = 0; nt < 8; nt++) {
                    const int c_l = cbase + nt * 8 + (lane & 3) * 2;
                    const float b0 = bsm[h * 128 + c_l], b1 = bsm[h * 128 + c_l + 1];
                    *(__nv_bfloat16*)(esp + c_l * 272 + m_l * 2)             = __float2bfloat16((acc[mt][nt][0] + b0) * r0);
                    *(__nv_bfloat16*)(esp + (c_l + 1) * 272 + m_l * 2)       = __float2bfloat16((acc[mt][nt][1] + b1) * r0);
                    *(__nv_bfloat16*)(esp + c_l * 272 + (m_l + 8) * 2)       = __float2bfloat16((acc[mt][nt][2] + b0) * r1);
                    *(__nv_bfloat16*)(esp + (c_l + 1) * 272 + (m_l + 8) * 2) = __float2bfloat16((acc[mt][nt][3] + b1) * r1);
                }
            }
        }
        __syncthreads();
#pragma unroll
        for (int t = 0; t < 4; t++) {
            int idx = tid + t * 512;
            int row = idx >> 4, q = idx & 15;
            float4 v = *(float4*)(esp + row * 272 + q * 16);
            *(float4*)&g_vs[((size_t)(b * C_ + h * 128 + row)) * N_ + m0 + q * 8] = v;
        }
    }
}

// ---------------------------------------------------------------------------
// K4: FUSED attention output (bf16), single barrier/chunk pipeline,
// all buffers double-buffered, 2 CTAs/SM.
// Per CTA: 64 n-rows x full C=256; 64 m-chunks of 64.
// smem: q [64x80] @0 | k 2st [64x80] @5120 | vs 2st [256x144] @15360 |
//       esm 2st [64x144] @89088  -> 107520 B  (2 CTA/SM: 215040 <= 227KB)
// ---------------------------------------------------------------------------
#define F_QOFF   0
#define F_KOFF   5120
#define F_KSTG   5120
#define F_VOFF   15360
#define F_VSTG   36864
#define F_EOFF   89088
#define F_ESTG   9216
#define F_SMEM   107520

__device__ __forceinline__ void f_load_k(uint32_t sbase, int st,
                                         const __nv_bfloat16* QK, int m0, int tid) {
    uint32_t ks = sbase + F_KOFF + st * F_KSTG;
    int row = tid >> 2, c16 = tid & 3;
    CP_ASYNC16(ks + row * 80 + c16 * 16, QK + (size_t)(m0 + row) * 64 + 32 + c16 * 8);
}
__device__ __forceinline__ void f_load_v(uint32_t sbase, int st,
                                         const __nv_bfloat16* Vb, int m0, int tid) {
    uint32_t vs = sbase + F_VOFF + st * F_VSTG;
#pragma unroll
    for (int t = 0; t < 8; t++) {
        int idx = tid + t * 256;
        int row = idx >> 3, c16 = idx & 7;
        CP_ASYNC16(vs + row * 144 + c16 * 16, Vb + (size_t)row * N_ + m0 + c16 * 8);
    }
}

// S = q k^T (bf16) -> exp (MUFU) -> esm[ebuf] (bf16)
__device__ __forceinline__ void f_s_phase(uint32_t sbase, char* smem, int kst, int ebuf,
                                          int warp_m, int warp_g, int lane,
                                          int lrow, int lcolB) {
    const uint32_t ks = sbase + F_KOFF + kst * F_KSTG;
    char* esp = smem + F_EOFF + ebuf * F_ESTG;

    float accs[2][2][4];
#pragma unroll
    for (int mt = 0; mt < 2; mt++)
#pragma unroll
        for (int u = 0; u < 2; u++)
#pragma unroll
            for (int r = 0; r < 4; r++) accs[mt][u][r] = 0.0f;

#pragma unroll
    for (int kk = 0; kk < 2; kk++) {
        const int kb = kk * 32 + lcolB;
        uint32_t a[2][4];
#pragma unroll
        for (int mt = 0; mt < 2; mt++)
            LDMATRIX_X4(a[mt][0], a[mt][1], a[mt][2], a[mt][3],
                        sbase + F_QOFF + (warp_m * 32 + mt * 16 + lrow) * 80 + kb);
        uint32_t bf[4];
        LDMATRIX_X4(bf[0], bf[1], bf[2], bf[3],
                    ks + (warp_g * 16 + lrow) * 80 + kb);
#pragma unroll
        for (int mt = 0; mt < 2; mt++)
#pragma unroll
            for (int u = 0; u < 2; u++)
                MMA_BF16(accs[mt][u], a[mt], bf[u], bf[u + 2]);
    }

#pragma unroll
    for (int mt = 0; mt < 2; mt++) {
        const int row = warp_m * 32 + mt * 16 + (lane >> 2);
#pragma unroll
        for (int u = 0; u < 2; u++) {
            const int col = warp_g * 16 + u * 8 + (lane & 3) * 2;
            float e0 = __expf(accs[mt][u][0]);
            float e1 = __expf(accs[mt][u][1]);
            float e2 = __expf(accs[mt][u][2]);
            float e3 = __expf(accs[mt][u][3]);
            __nv_bfloat162 p01, p23;
            p01.x = __float2bfloat16(e0); p01.y = __float2bfloat16(e1);
            p23.x = __float2bfloat16(e2); p23.y = __float2bfloat16(e3);
            *(__nv_bfloat162*)(esp + row * 144 + col * 2)       = p01;
            *(__nv_bfloat162*)(esp + (row + 8) * 144 + col * 2) = p23;
        }
    }
}

// out += esm[ebuf](64n x 64m) @ vs[vst](256c x 64m)^T
__device__ __forceinline__ void f_out_phase(uint32_t sbase, int vst, int ebuf,
                                            float acco[2][8][4],
                                            int warp_m, int warp_g,
                                            int lrow, int lcolB) {
    const uint32_t vsm = sbase + F_VOFF + vst * F_VSTG;
    const uint32_t esm = sbase + F_EOFF + ebuf * F_ESTG;
#pragma unroll
    for (int kk = 0; kk < 4; kk++) {
        const int kb = kk * 32 + lcolB;
        uint32_t ae[2][4];
#pragma unroll
        for (int mt = 0; mt < 2; mt++)
            LDMATRIX_X4(ae[mt][0], ae[mt][1], ae[mt][2], ae[mt][3],
                        esm + (warp_m * 32 + mt * 16 + lrow) * 144 + kb);
        uint32_t be[4][4];
#pragma unroll
        for (int bt = 0; bt < 4; bt++)
            LDMATRIX_X4(be[bt][0], be[bt][1], be[bt][2], be[bt][3],
                        vsm + (warp_g * 64 + bt * 16 + lrow) * 144 + kb);
#pragma unroll
        for (int mt = 0; mt < 2; mt++)
#pragma unroll
            for (int nt = 0; nt < 8; nt++) {
                const int bt = nt >> 1, sel = nt & 1;
                MMA_BF16(acco[mt][nt], ae[mt], be[bt][sel], be[bt][sel + 2]);
            }
    }
}

__global__ __launch_bounds__(256, 2) void attn_fused(const float* __restrict__ x,
                                                     const float* __restrict__ gamma,
                                                     float* __restrict__ out) {
    extern __shared__ char smem[];
    const uint32_t sbase = smem_u32(smem);

    const int tid  = threadIdx.x;
    const int wid  = tid >> 5;
    const int lane = tid & 31;
    const int b    = blockIdx.y;
    const int n0   = blockIdx.x * 64;
    const int warp_m = wid & 1;      // 32 n-rows
    const int warp_g = wid >> 1;     // 0..3
    const int lrow  = lane & 15;
    const int lcolB = (lane >> 4) * 16;

    const __nv_bfloat16* QK = g_qkh + (size_t)b * N_ * 64;
    const __nv_bfloat16* Vb = g_vs + (size_t)b * C_ * N_;

    // prologue: P0 = [q, k(0), vs(0)], P1 = [k(1)]
    {
        int row = tid >> 2, c16 = tid & 3;
        CP_ASYNC16(sbase + F_QOFF + row * 80 + c16 * 16, QK + (size_t)(n0 + row) * 64 + c16 * 8);
    }
    f_load_k(sbase, 0, QK, 0, tid);
    f_load_v(sbase, 0, Vb, 0, tid);
    CP_COMMIT();
    f_load_k(sbase, 1, QK, 64, tid);
    CP_COMMIT();

    float acco[2][8][4];
#pragma unroll
    for (int mt = 0; mt < 2; mt++)
#pragma unroll
        for (int nt = 0; nt < 8; nt++)
#pragma unroll
            for (int r = 0; r < 4; r++) acco[mt][nt][r] = 0.0f;

    CP_WAIT1();                 // P0 done: q, k(0), vs(0)
    __syncthreads();
    f_s_phase(sbase, smem, 0, 0, warp_m, warp_g, lane, lrow, lcolB);   // S(0) -> esm0

    for (int mc = 0; mc < 64; mc++) {
        CP_WAIT0();             // [k(mc+1), vs(mc)] landed
        __syncthreads();        // stage ownership + esm visibility

        // prefetch: k(mc+2) -> stage mc&1 (S(mc) done), vs(mc+1) -> stage (mc+1)&1
        bool cm = false;
        if (mc + 2 < 64) { f_load_k(sbase, mc & 1, QK, (mc + 2) * 64, tid); cm = true; }
        if (mc + 1 < 64) { f_load_v(sbase, (mc + 1) & 1, Vb, (mc + 1) * 64, tid); cm = true; }
        if (cm) CP_COMMIT();

        // out(mc): fills tensor pipe, no fresh deps
        f_out_phase(sbase, mc & 1, mc & 1, acco, warp_m, warp_g, lrow, lcolB);

        // S(mc+1) -> other esm buffer (k(mc+1) already resident)
        if (mc + 1 < 64)
            f_s_phase(sbase, smem, (mc + 1) & 1, (mc + 1) & 1,
                      warp_m, warp_g, lane, lrow, lcolB);
    }

    // ---------------- epilogue: two c-halves, transpose via smem
    const float g = __ldg(gamma);
    float* so = (float*)smem;                 // [128 c][68 n] fp32 = 34816 B

#pragma unroll
    for (int h = 0; h < 2; h++) {
        __syncthreads();
        if ((warp_g >> 1) == h) {
            const int cbase = (warp_g & 1) * 64;
#pragma unroll
            for (int mt = 0; mt < 2; mt++) {
                const int n_l = warp_m * 32 + mt * 16 + (lane >> 2);
#pragma unroll
                for (int nt = 0; nt < 8; nt++) {
                    const int c_l = cbase + nt * 8 + (lane & 3) * 2;
                    so[c_l * 68 + n_l]           = acco[mt][nt][0];
                    so[(c_l + 1) * 68 + n_l]     = acco[mt][nt][1];
                    so[c_l * 68 + n_l + 8]       = acco[mt][nt][2];
                    so[(c_l + 1) * 68 + n_l + 8] = acco[mt][nt][3];
                }
            }
        }
        __syncthreads();
#pragma unroll
        for (int t = 0; t < 8; t++) {
            int idx = tid + t * 256;
            int c_l = idx >> 4, q = idx & 15;
            float4 v = *(float4*)&so[c_l * 68 + q * 4];
            size_t gi = ((size_t)(b * C_ + h * 128 + c_l)) * N_ + n0 + q * 4;
            float4 xv = *(const float4*)&x[gi];
            float4 o;
            o.x = g * v.x + xv.x;
            o.y = g * v.y + xv.y;
            o.z = g * v.z + xv.z;
            o.w = g * v.w + xv.w;
            *(float4*)&out[gi] = o;
        }
    }
}

// ---------------------------------------------------------------------------
extern "C" void kernel_launch(void* const* d_in, const int* in_sizes, int n_in,
                              void* d_out, int out_size) {
    const float* x     = (const float*)d_in[0];
    const float* Wq    = (const float*)d_in[1];
    const float* bq    = (const float*)d_in[2];
    const float* Wk    = (const float*)d_in[3];
    const float* bk    = (const float*)d_in[4];
    const float* Wv    = (const float*)d_in[5];
    const float* bv    = (const float*)d_in[6];
    const float* gamma = (const float*)d_in[7];
    float* out = (float*)d_out;

    cudaFuncSetAttribute(proj_qk_fused, cudaFuncAttributeMaxDynamicSharedMemorySize, Q_SMEM);
    cudaFuncSetAttribute(proj_v_mma,    cudaFuncAttributeMaxDynamicSharedMemorySize, K3_SMEM);
    cudaFuncSetAttribute(attn_fused,    cudaFuncAttributeMaxDynamicSharedMemorySize, F_SMEM);

    proj_qk_fused<<<dim3(N_ / 128, B_), 256, Q_SMEM>>>(x, Wq, bq, Wk, bk);
    lsum_mma<<<dim3(N_ / 64, B_), 256>>>();
    proj_v_mma<<<dim3(N_ / 128, B_), 512, K3_SMEM>>>(Wv, bv);
    attn_fused<<<dim3(N_ / 64, B_), 256, F_SMEM>>>(x, gamma, out);
}